// round 1
// baseline (speedup 1.0000x reference)
#include <cuda_runtime.h>
#include <cuda_bf16.h>
#include <math.h>

// ---------------------------------------------------------------------------
// Problem constants
// ---------------------------------------------------------------------------
#define BB   4
#define TT   2048
#define CC   1024
#define HH   16
#define HS   64
#define CUT  1024          // min(T, CTX/2^LAYER) = 1024
#define ROWS_FULL (BB*TT)  // 8192
#define ROWS_CUT  (BB*CUT) // 4096
#define SCALE 0.03125f     // C^-0.5 = 1/32

// ---------------------------------------------------------------------------
// Scratch (device globals -- no allocation allowed)
// ---------------------------------------------------------------------------
__device__ float g_h  [ROWS_FULL * CC];          // ln1 output           32MB
__device__ float g_K  [BB*HH*TT*HS];             // K [b,h,t,d]          32MB
__device__ float g_V  [BB*HH*TT*HS];             // V [b,h,t,d]          32MB
__device__ float g_Q  [BB*HH*CUT*HS];            // Q [b,h,s,d]          16MB
__device__ float g_o  [ROWS_CUT * CC];           // attn out concat      16MB
__device__ float g_res[ROWS_CUT * CC];           // residual 1           16MB
__device__ float g_h2 [ROWS_CUT * CC];           // ln2 output           16MB
__device__ float g_a1 [ROWS_CUT * 4*CC];         // gelu(lin1)           64MB
__device__ float g_Wt [3 * CC * CC];             // repacked Wq,Wk,Wv    12MB

// ---------------------------------------------------------------------------
// Repack [H,C,HS] -> [C, H*HS] for Wq/Wk/Wv
// ---------------------------------------------------------------------------
__global__ void repack_kernel(const float* __restrict__ Wq,
                              const float* __restrict__ Wk,
                              const float* __restrict__ Wv,
                              float* __restrict__ out)
{
    int idx = blockIdx.x * 256 + threadIdx.x;     // 0 .. 1M-1
    int w   = blockIdx.y;                          // 0,1,2
    const float* W = (w == 0) ? Wq : ((w == 1) ? Wk : Wv);
    int c = idx >> 10;
    int j = idx & 1023;
    int h = j >> 6, d = j & 63;
    out[w * (CC*CC) + idx] = W[h * (CC*HS) + c * HS + d];
}

// ---------------------------------------------------------------------------
// LayerNorm: one block per row of 1024 floats, 256 threads (1 float4 each)
// ---------------------------------------------------------------------------
__global__ void ln_kernel(const float* __restrict__ in, float* __restrict__ out,
                          const float* __restrict__ w, const float* __restrict__ b)
{
    int row = blockIdx.x;
    int tid = threadIdx.x;
    const float4 x4 = ((const float4*)(in + (size_t)row * CC))[tid];
    float s  = x4.x + x4.y + x4.z + x4.w;
    float s2 = x4.x*x4.x + x4.y*x4.y + x4.z*x4.z + x4.w*x4.w;

    // warp reduce
    #pragma unroll
    for (int off = 16; off > 0; off >>= 1) {
        s  += __shfl_xor_sync(0xffffffffu, s,  off);
        s2 += __shfl_xor_sync(0xffffffffu, s2, off);
    }
    __shared__ float red[2][8];
    int wid = tid >> 5, lane = tid & 31;
    if (lane == 0) { red[0][wid] = s; red[1][wid] = s2; }
    __syncthreads();
    float ts = 0.f, ts2 = 0.f;
    #pragma unroll
    for (int i = 0; i < 8; i++) { ts += red[0][i]; ts2 += red[1][i]; }

    float mean = ts * (1.0f / CC);
    float var  = ts2 * (1.0f / CC) - mean * mean;
    float rstd = rsqrtf(var + 1e-5f);

    const float4 w4 = ((const float4*)w)[tid];
    const float4 b4 = ((const float4*)b)[tid];
    float4 o4;
    o4.x = (x4.x - mean) * rstd * w4.x + b4.x;
    o4.y = (x4.y - mean) * rstd * w4.y + b4.y;
    o4.z = (x4.z - mean) * rstd * w4.z + b4.z;
    o4.w = (x4.w - mean) * rstd * w4.w + b4.w;
    ((float4*)(out + (size_t)row * CC))[tid] = o4;
}

// ---------------------------------------------------------------------------
// SGEMM: C[M,N] = A[M,K] @ B[K,N] (+ bias, epilogue variants)
//   BM=128, BN=64, BK=16, 256 threads, thread tile 8x4
// AMAP: 0 = identity rows, 1 = last-CUT rows of [B,T] layout
// EPI : 0 plain, 1 scatter to [b,h,t,d] (Td param), 2 +resid(Qmap x),
//       3 gelu, 4 +resid(identity)
// ---------------------------------------------------------------------------
__device__ __forceinline__ float gelu_exact(float x)
{
    return 0.5f * x * (1.0f + erff(x * 0.70710678118654752440f));
}

template<int AMAP, int EPI>
__global__ void __launch_bounds__(256, 2)
sgemm_kernel(const float* __restrict__ A, const float* __restrict__ B,
             float* __restrict__ C, const float* __restrict__ bias,
             const float* __restrict__ resid,
             int M, int N, int K, int Td)
{
    __shared__ float As[16][132];     // [k][m], padded
    __shared__ float Bs[16][64];      // [k][n]

    const int tid = threadIdx.x;
    const int m0 = blockIdx.y * 128;
    const int n0 = blockIdx.x * 64;
    const int ty = tid >> 4;          // 0..15 -> rows ty*8..+7
    const int tx = tid & 15;          // 0..15 -> cols tx*4..+3

    float acc[8][4];
    #pragma unroll
    for (int i = 0; i < 8; i++)
        #pragma unroll
        for (int j = 0; j < 4; j++) acc[i][j] = 0.f;

    for (int kt = 0; kt < K; kt += 16) {
        // load A tile (128x16) transposed into As
        #pragma unroll
        for (int p = 0; p < 2; p++) {
            int lin4 = p * 256 + tid;          // float4 index, 512 total
            int r = lin4 >> 2;                 // 0..127
            int c = (lin4 & 3) * 4;            // 0,4,8,12
            int row = m0 + r;
            int arow = AMAP ? ((row >> 10) * TT + (TT - CUT) + (row & (CUT-1))) : row;
            float4 a = *(const float4*)(A + (size_t)arow * K + kt + c);
            As[c+0][r] = a.x; As[c+1][r] = a.y; As[c+2][r] = a.z; As[c+3][r] = a.w;
        }
        // load B tile (16x64)
        {
            int r = tid >> 4;
            int c = (tid & 15) * 4;
            float4 b4 = *(const float4*)(B + (size_t)(kt + r) * N + n0 + c);
            *(float4*)&Bs[r][c] = b4;
        }
        __syncthreads();

        #pragma unroll
        for (int k = 0; k < 16; k++) {
            float ar[8], br[4];
            *(float4*)(ar)     = *(const float4*)&As[k][ty*8];
            *(float4*)(ar + 4) = *(const float4*)&As[k][ty*8 + 4];
            *(float4*)(br)     = *(const float4*)&Bs[k][tx*4];
            #pragma unroll
            for (int i = 0; i < 8; i++)
                #pragma unroll
                for (int j = 0; j < 4; j++)
                    acc[i][j] += ar[i] * br[j];
        }
        __syncthreads();
    }

    // epilogue
    #pragma unroll
    for (int i = 0; i < 8; i++) {
        int gi = m0 + ty * 8 + i;
        #pragma unroll
        for (int j = 0; j < 4; j++) {
            int gj = n0 + tx * 4 + j;
            float v = acc[i][j] + bias[gj];
            if (EPI == 1) {
                int b_ = gi / Td, t = gi % Td;
                int h = gj >> 6, d = gj & 63;
                C[(((size_t)b_ * HH + h) * Td + t) * HS + d] = v;
            } else if (EPI == 2) {
                int xrow = (gi >> 10) * TT + (TT - CUT) + (gi & (CUT-1));
                C[(size_t)gi * N + gj] = v + resid[(size_t)xrow * N + gj];
            } else if (EPI == 3) {
                C[(size_t)gi * N + gj] = gelu_exact(v);
            } else if (EPI == 4) {
                C[(size_t)gi * N + gj] = v + resid[(size_t)gi * N + gj];
            } else {
                C[(size_t)gi * N + gj] = v;
            }
        }
    }
}

// ---------------------------------------------------------------------------
// Flash attention: grid (qt=16, bh=64), 256 threads.
// 64 queries x HS=64 per block; loop over 64-wide key tiles with online softmax.
// smem: Qt[64][64] ([d][i]) | KtPs[64][68] (K^T then reused for P) | Vs[64][64]
// ---------------------------------------------------------------------------
__global__ void __launch_bounds__(256, 2)
attn_kernel(const float* __restrict__ Qg, const float* __restrict__ Kg,
            const float* __restrict__ Vg, float* __restrict__ O)
{
    extern __shared__ float sm[];
    float* Qt   = sm;                 // 64*64
    float* KtPs = sm + 64*64;         // 64*68
    float* Vs   = KtPs + 64*68;       // 64*64

    const int qt  = blockIdx.x;       // 0..15
    const int bh  = blockIdx.y;       // 0..63
    const int tid = threadIdx.x;
    const int tx  = tid & 15;         // j/d group
    const int ty  = tid >> 4;         // i group

    const size_t kvbase = (size_t)bh * TT * HS;
    const size_t qbase  = (size_t)bh * CUT * HS + (size_t)qt * 64 * HS;

    // load Q tile transposed -> Qt[d][i]
    #pragma unroll
    for (int p = 0; p < 4; p++) {
        int lin4 = p * 256 + tid;            // 1024 float4
        int r = lin4 >> 4;                   // 0..63  (query row)
        int d = (lin4 & 15) * 4;
        float4 q4 = *(const float4*)(Qg + qbase + (size_t)r * HS + d);
        Qt[(d+0)*64 + r] = q4.x; Qt[(d+1)*64 + r] = q4.y;
        Qt[(d+2)*64 + r] = q4.z; Qt[(d+3)*64 + r] = q4.w;
    }

    float m[4], l[4], o[4][4];
    #pragma unroll
    for (int i = 0; i < 4; i++) {
        m[i] = -1e30f; l[i] = 0.f;
        #pragma unroll
        for (int j = 0; j < 4; j++) o[i][j] = 0.f;
    }

    const int ktmax = (TT - CUT) / 64 + qt;   // inclusive; last tile is diagonal

    for (int kt = 0; kt <= ktmax; kt++) {
        __syncthreads();   // protect Qt (first iter) / Ps,Vs (later iters)
        // load K tile transposed + V tile natural
        #pragma unroll
        for (int p = 0; p < 4; p++) {
            int lin4 = p * 256 + tid;
            int r = lin4 >> 4;
            int d = (lin4 & 15) * 4;
            const size_t gaddr = kvbase + (size_t)(kt*64 + r) * HS + d;
            float4 k4 = *(const float4*)(Kg + gaddr);
            KtPs[(d+0)*68 + r] = k4.x; KtPs[(d+1)*68 + r] = k4.y;
            KtPs[(d+2)*68 + r] = k4.z; KtPs[(d+3)*68 + r] = k4.w;
            float4 v4 = *(const float4*)(Vg + gaddr);
            *(float4*)&Vs[r*64 + d] = v4;
        }
        __syncthreads();

        // S = Q K^T * scale
        float s[4][4];
        #pragma unroll
        for (int i = 0; i < 4; i++)
            #pragma unroll
            for (int j = 0; j < 4; j++) s[i][j] = 0.f;

        #pragma unroll 8
        for (int d = 0; d < 64; d++) {
            float4 qv = *(const float4*)&Qt[d*64 + ty*4];
            float4 kv = *(const float4*)&KtPs[d*68 + tx*4];
            float qa[4] = {qv.x, qv.y, qv.z, qv.w};
            float ka[4] = {kv.x, kv.y, kv.z, kv.w};
            #pragma unroll
            for (int i = 0; i < 4; i++)
                #pragma unroll
                for (int j = 0; j < 4; j++)
                    s[i][j] += qa[i] * ka[j];
        }
        #pragma unroll
        for (int i = 0; i < 4; i++)
            #pragma unroll
            for (int j = 0; j < 4; j++) s[i][j] *= SCALE;

        if (kt == ktmax) {   // diagonal tile: mask j > i
            #pragma unroll
            for (int i = 0; i < 4; i++)
                #pragma unroll
                for (int j = 0; j < 4; j++)
                    if (tx*4 + j > ty*4 + i) s[i][j] = -1e30f;
        }

        // row max across tile
        float mt[4];
        #pragma unroll
        for (int i = 0; i < 4; i++) {
            mt[i] = fmaxf(fmaxf(s[i][0], s[i][1]), fmaxf(s[i][2], s[i][3]));
            #pragma unroll
            for (int off = 8; off > 0; off >>= 1)
                mt[i] = fmaxf(mt[i], __shfl_xor_sync(0xffffffffu, mt[i], off, 16));
        }

        float ls[4];
        #pragma unroll
        for (int i = 0; i < 4; i++) {
            float mnew = fmaxf(m[i], mt[i]);
            float sc = __expf(m[i] - mnew);
            m[i] = mnew;
            float acc = 0.f;
            #pragma unroll
            for (int j = 0; j < 4; j++) {
                s[i][j] = __expf(s[i][j] - mnew);
                acc += s[i][j];
            }
            ls[i] = acc;
            l[i] = l[i] * sc;
            #pragma unroll
            for (int j = 0; j < 4; j++) o[i][j] *= sc;
        }
        #pragma unroll
        for (int i = 0; i < 4; i++) {
            #pragma unroll
            for (int off = 8; off > 0; off >>= 1)
                ls[i] += __shfl_xor_sync(0xffffffffu, ls[i], off, 16);
            l[i] += ls[i];
        }

        __syncthreads();   // everyone done reading Kt
        // write P tile into KtPs as [i][j], stride 68
        #pragma unroll
        for (int i = 0; i < 4; i++) {
            float4 pv = make_float4(s[i][0], s[i][1], s[i][2], s[i][3]);
            *(float4*)&KtPs[(ty*4 + i)*68 + tx*4] = pv;
        }
        __syncthreads();

        // O += P @ V
        #pragma unroll 8
        for (int j = 0; j < 64; j++) {
            float4 vv = *(const float4*)&Vs[j*64 + tx*4];
            float va[4] = {vv.x, vv.y, vv.z, vv.w};
            float pr[4];
            #pragma unroll
            for (int i = 0; i < 4; i++) pr[i] = KtPs[(ty*4 + i)*68 + j];
            #pragma unroll
            for (int i = 0; i < 4; i++)
                #pragma unroll
                for (int jj = 0; jj < 4; jj++)
                    o[i][jj] += pr[i] * va[jj];
        }
    }

    // write O (head-concat layout [b, s, h*64+d])
    const int b_ = bh >> 4, h_ = bh & 15;
    #pragma unroll
    for (int i = 0; i < 4; i++) {
        int srow = qt * 64 + ty * 4 + i;
        float inv = 1.0f / l[i];
        float4 ov = make_float4(o[i][0]*inv, o[i][1]*inv, o[i][2]*inv, o[i][3]*inv);
        size_t addr = ((size_t)b_ * CUT + srow) * CC + h_ * HS + tx * 4;
        *(float4*)(O + addr) = ov;
    }
}

// ---------------------------------------------------------------------------
// Launch
// ---------------------------------------------------------------------------
extern "C" void kernel_launch(void* const* d_in, const int* in_sizes, int n_in,
                              void* d_out, int out_size)
{
    const float* x      = (const float*)d_in[0];
    const float* ln1_w  = (const float*)d_in[1];
    const float* ln1_b  = (const float*)d_in[2];
    const float* Wq     = (const float*)d_in[3];
    const float* bq     = (const float*)d_in[4];
    const float* Wk     = (const float*)d_in[5];
    const float* bk     = (const float*)d_in[6];
    const float* Wv     = (const float*)d_in[7];
    const float* bv     = (const float*)d_in[8];
    const float* proj_w = (const float*)d_in[9];
    const float* proj_b = (const float*)d_in[10];
    const float* ln2_w  = (const float*)d_in[11];
    const float* ln2_b  = (const float*)d_in[12];
    const float* lin1_w = (const float*)d_in[13];
    const float* lin1_b = (const float*)d_in[14];
    const float* lin2_w = (const float*)d_in[15];
    const float* lin2_b = (const float*)d_in[16];
    float* out = (float*)d_out;

    float *p_h, *p_K, *p_V, *p_Q, *p_o, *p_res, *p_h2, *p_a1, *p_Wt;
    cudaGetSymbolAddress((void**)&p_h,  g_h);
    cudaGetSymbolAddress((void**)&p_K,  g_K);
    cudaGetSymbolAddress((void**)&p_V,  g_V);
    cudaGetSymbolAddress((void**)&p_Q,  g_Q);
    cudaGetSymbolAddress((void**)&p_o,  g_o);
    cudaGetSymbolAddress((void**)&p_res,g_res);
    cudaGetSymbolAddress((void**)&p_h2, g_h2);
    cudaGetSymbolAddress((void**)&p_a1, g_a1);
    cudaGetSymbolAddress((void**)&p_Wt, g_Wt);

    static bool attr_set = false;
    if (!attr_set) {
        cudaFuncSetAttribute(attn_kernel,
                             cudaFuncAttributeMaxDynamicSharedMemorySize, 50176);
        attr_set = true;
    }

    // repack Wq/Wk/Wv -> [C, H*HS]
    repack_kernel<<<dim3(CC*CC/256, 3), 256>>>(Wq, Wk, Wv, p_Wt);

    // LN1
    ln_kernel<<<ROWS_FULL, 256>>>(x, p_h, ln1_w, ln1_b);

    // K, V projections over all 8192 rows
    dim3 gKV(CC/64, ROWS_FULL/128);            // (16, 64)
    sgemm_kernel<0,1><<<gKV, 256>>>(p_h, p_Wt + 1*CC*CC, p_K, bk, nullptr,
                                    ROWS_FULL, CC, CC, TT);
    sgemm_kernel<0,1><<<gKV, 256>>>(p_h, p_Wt + 2*CC*CC, p_V, bv, nullptr,
                                    ROWS_FULL, CC, CC, TT);
    // Q projection over last CUT rows
    dim3 gQ(CC/64, ROWS_CUT/128);              // (16, 32)
    sgemm_kernel<1,1><<<gQ, 256>>>(p_h, p_Wt, p_Q, bq, nullptr,
                                   ROWS_CUT, CC, CC, CUT);

    // attention
    attn_kernel<<<dim3(CUT/64, BB*HH), 256, 50176>>>(p_Q, p_K, p_V, p_o);

    // proj + residual(x last cut)
    sgemm_kernel<0,2><<<gQ, 256>>>(p_o, proj_w, p_res, proj_b, x,
                                   ROWS_CUT, CC, CC, 0);

    // LN2
    ln_kernel<<<ROWS_CUT, 256>>>(p_res, p_h2, ln2_w, ln2_b);

    // MLP
    dim3 gL1(4*CC/64, ROWS_CUT/128);           // (64, 32)
    sgemm_kernel<0,3><<<gL1, 256>>>(p_h2, lin1_w, p_a1, lin1_b, nullptr,
                                    ROWS_CUT, 4*CC, CC, 0);
    sgemm_kernel<0,4><<<gQ, 256>>>(p_a1, lin2_w, out, lin2_b, p_res,
                                   ROWS_CUT, CC, 4*CC, 0);
}

// round 7
// speedup vs baseline: 2.4075x; 2.4075x over previous
#include <cuda_runtime.h>
#include <cuda_bf16.h>
#include <cstdint>
#include <math.h>

// ---------------------------------------------------------------------------
// Problem constants
// ---------------------------------------------------------------------------
#define BB   4
#define TT   2048
#define CC   1024
#define HH   16
#define HS   64
#define CUT  1024
#define ROWS_FULL (BB*TT)   // 8192
#define ROWS_CUT  (BB*CUT)  // 4096
#define SCALE 0.03125f      // C^-0.5

// ---------------------------------------------------------------------------
// Scratch (device globals; no allocations allowed)
// ---------------------------------------------------------------------------
__device__ float g_h   [ROWS_FULL * CC];
__device__ float g_K   [BB*HH*TT*HS];
__device__ float g_V   [BB*HH*TT*HS];
__device__ float g_Q   [BB*HH*CUT*HS];
__device__ float g_o   [ROWS_CUT * CC];
__device__ float g_res [ROWS_CUT * CC];
__device__ float g_h2  [ROWS_CUT * CC];
__device__ float g_a1  [ROWS_CUT * 4*CC];
__device__ float g_Wqkv[3 * CC * CC];     // [3072, 1024] K-major (N rows, K cols)
__device__ float g_Wp  [CC * CC];         // [1024, 1024] K-major
__device__ float g_W1  [4*CC * CC];       // [4096, 1024] K-major
__device__ float g_W2  [CC * 4*CC];       // [1024, 4096] K-major
__device__ float g_bqkv[3 * CC];

// ---------------------------------------------------------------------------
// Helpers
// ---------------------------------------------------------------------------
__device__ __forceinline__ uint32_t smem_u32(const void* p) {
    uint32_t a;
    asm("{ .reg .u64 t; cvta.to.shared.u64 t, %1; cvt.u32.u64 %0, t; }"
        : "=r"(a) : "l"(p));
    return a;
}
// round fp32 -> tf32 (nearest) so HW tf32 truncation is a no-op
__device__ __forceinline__ float rtf32(float x) {
    uint32_t u = __float_as_uint(x);
    u = (u + 0x1000u) & 0xFFFFE000u;
    return __uint_as_float(u);
}
__device__ __forceinline__ float gelu_exact(float x) {
    return 0.5f * x * (1.0f + erff(x * 0.70710678118654752440f));
}

#define CP_ASYNC16(dst, src) \
    asm volatile("cp.async.cg.shared.global [%0], [%1], 16;" :: "r"(dst), "l"(src))
#define CP_COMMIT() asm volatile("cp.async.commit_group;")
#define CP_WAIT(n)  asm volatile("cp.async.wait_group %0;" :: "n"(n))

#define LDSM_X4(r0, r1, r2, r3, a) \
    asm volatile("ldmatrix.sync.aligned.m8n8.x4.shared.b16 {%0,%1,%2,%3}, [%4];" \
        : "=r"(r0), "=r"(r1), "=r"(r2), "=r"(r3) : "r"(a))

__device__ __forceinline__ void mma_tf32(float* c, const uint32_t* a, const uint32_t* b) {
    asm volatile(
        "mma.sync.aligned.m16n8k8.row.col.f32.tf32.tf32.f32 "
        "{%0,%1,%2,%3}, {%4,%5,%6,%7}, {%8,%9}, {%0,%1,%2,%3};"
        : "+f"(c[0]), "+f"(c[1]), "+f"(c[2]), "+f"(c[3])
        : "r"(a[0]), "r"(a[1]), "r"(a[2]), "r"(a[3]), "r"(b[0]), "r"(b[1]));
}

// ---------------------------------------------------------------------------
// Transpose + round: dst[n*K+k] = rtf32(src[k*N+n])
// ---------------------------------------------------------------------------
__global__ void tr_kernel(const float* __restrict__ src, float* __restrict__ dst,
                          int K, int N)
{
    __shared__ float t[32][33];
    int k0 = blockIdx.y * 32, n0 = blockIdx.x * 32;
    int tx = threadIdx.x, ty = threadIdx.y;      // 32 x 8
    #pragma unroll
    for (int i = 0; i < 32; i += 8)
        t[ty + i][tx] = src[(size_t)(k0 + ty + i) * N + n0 + tx];
    __syncthreads();
    #pragma unroll
    for (int i = 0; i < 32; i += 8)
        dst[(size_t)(n0 + ty + i) * K + k0 + tx] = rtf32(t[tx][ty + i]);
}

// QKV: [H,C,HS] x3 -> [3072, 1024] K-major; batch z: w=z/16, h=z%16
__global__ void qkv_tr_kernel(const float* __restrict__ Wq,
                              const float* __restrict__ Wk,
                              const float* __restrict__ Wv,
                              float* __restrict__ dst)
{
    __shared__ float t[32][33];
    int z = blockIdx.z, w = z >> 4, h = z & 15;
    const float* W = (w == 0) ? Wq : ((w == 1) ? Wk : Wv);
    const float* src = W + (size_t)h * CC * HS;          // [1024 c, 64 d]
    float* d = dst + (size_t)w * CC * CC + (size_t)(h * HS) * CC;
    int k0 = blockIdx.y * 32, n0 = blockIdx.x * 32;
    int tx = threadIdx.x, ty = threadIdx.y;
    #pragma unroll
    for (int i = 0; i < 32; i += 8)
        t[ty + i][tx] = src[(size_t)(k0 + ty + i) * HS + n0 + tx];
    __syncthreads();
    #pragma unroll
    for (int i = 0; i < 32; i += 8)
        d[(size_t)(n0 + ty + i) * CC + k0 + tx] = rtf32(t[tx][ty + i]);
}

__global__ void bias_pack_kernel(const float* __restrict__ bq,
                                 const float* __restrict__ bk,
                                 const float* __restrict__ bv,
                                 float* __restrict__ out)
{
    int w = blockIdx.x, i = threadIdx.x;
    const float* b = (w == 0) ? bq : ((w == 1) ? bk : bv);
    out[w * CC + i] = b[i];
}

// ---------------------------------------------------------------------------
// LayerNorm (rounds output to tf32 — it only feeds GEMMs)
// ---------------------------------------------------------------------------
__global__ void ln_kernel(const float* __restrict__ in, float* __restrict__ out,
                          const float* __restrict__ w, const float* __restrict__ b)
{
    int row = blockIdx.x;
    int tid = threadIdx.x;
    const float4 x4 = ((const float4*)(in + (size_t)row * CC))[tid];
    float s  = x4.x + x4.y + x4.z + x4.w;
    float s2 = x4.x*x4.x + x4.y*x4.y + x4.z*x4.z + x4.w*x4.w;
    #pragma unroll
    for (int off = 16; off > 0; off >>= 1) {
        s  += __shfl_xor_sync(0xffffffffu, s,  off);
        s2 += __shfl_xor_sync(0xffffffffu, s2, off);
    }
    __shared__ float red[2][8];
    int wid = tid >> 5, lane = tid & 31;
    if (lane == 0) { red[0][wid] = s; red[1][wid] = s2; }
    __syncthreads();
    float ts = 0.f, ts2 = 0.f;
    #pragma unroll
    for (int i = 0; i < 8; i++) { ts += red[0][i]; ts2 += red[1][i]; }
    float mean = ts * (1.0f / CC);
    float var  = ts2 * (1.0f / CC) - mean * mean;
    float rstd = rsqrtf(var + 1e-5f);
    const float4 w4 = ((const float4*)w)[tid];
    const float4 b4 = ((const float4*)b)[tid];
    float4 o4;
    o4.x = rtf32((x4.x - mean) * rstd * w4.x + b4.x);
    o4.y = rtf32((x4.y - mean) * rstd * w4.y + b4.y);
    o4.z = rtf32((x4.z - mean) * rstd * w4.z + b4.z);
    o4.w = rtf32((x4.w - mean) * rstd * w4.w + b4.w);
    ((float4*)(out + (size_t)row * CC))[tid] = o4;
}

// ---------------------------------------------------------------------------
// Tensor-core tf32 GEMM via mma.sync (m16n8k8), portable to base sm_103.
//   C[M,N] = A[M,K] @ Bt[N,K]^T (+bias, epilogues)
// CTA 128x128, BK=32, 256 threads: 8 warps as 2(M) x 4(N), warp tile 64x32.
// SMEM per stage: A[128][32] + B[128][32] fp32, XOR-swizzled on 16B groups,
// 3 stages, cp.async pipeline.
// EPI: 1 = QKV scatter (C=Q, R1=K, R2=V), 2 = +x residual (row remap) -> C,
//      3 = gelu+round -> C, 4 = +R1 residual -> C
// ---------------------------------------------------------------------------
#define GEMM_SMEM (3 * 8192 * 4)   // 96 KB

template<int EPI>
__global__ void __launch_bounds__(256)
tc_gemm(const float* __restrict__ A, const float* __restrict__ Bt,
        float* __restrict__ C, const float* __restrict__ bias,
        const float* __restrict__ R1, const float* __restrict__ R2,
        int M, int N, int K)
{
    extern __shared__ float sm[];     // 3 stages x (4096 A + 4096 B) floats
    __shared__ float sbias[128];

    const int tid  = threadIdx.x;
    const int lane = tid & 31;
    const int warp = tid >> 5;
    const int wm   = warp & 1;        // 0..1  (M dim)
    const int wn   = warp >> 1;       // 0..3  (N dim)
    const int m0   = blockIdx.y * 128;
    const int n0   = blockIdx.x * 128;

    if (tid < 128) sbias[tid] = bias[n0 + tid];

    const uint32_t smb = smem_u32(sm);
    const int nt = K >> 5;            // number of 32-wide K chunks

    // ---- tile loader: A[128][32] + B[128][32], swizzled ----
    // 1024 16B chunks per tile: lin = i*256+tid (i<4), row = lin>>3, g = lin&7
    auto load_tile = [&](int it) {
        const int s = it % 3;
        const uint32_t sa = smb + (uint32_t)s * 32768u;           // A stage base
        const uint32_t sb = sa + 16384u;                          // B stage base
        const float* gA = A  + (size_t)it * 32;
        const float* gB = Bt + (size_t)it * 32;
        #pragma unroll
        for (int i = 0; i < 4; i++) {
            int lin = i * 256 + tid;
            int r = lin >> 3;                 // 0..127
            int g = lin & 7;                  // 16B group within 32-float row
            uint32_t off = (uint32_t)(r * 32 + ((g ^ (r & 7)) * 4)) * 4u;
            CP_ASYNC16(sa + off, gA + (size_t)(m0 + r) * K + g * 4);
            CP_ASYNC16(sb + off, gB + (size_t)(n0 + r) * K + g * 4);
        }
        CP_COMMIT();
    };

    float acc[4][4][4];
    #pragma unroll
    for (int i = 0; i < 4; i++)
        #pragma unroll
        for (int j = 0; j < 4; j++)
            #pragma unroll
            for (int k = 0; k < 4; k++) acc[i][j][k] = 0.f;

    // per-thread ldmatrix row indices (within CTA tile)
    int rA[4], rB[2];
    #pragma unroll
    for (int mf = 0; mf < 4; mf++) rA[mf] = wm * 64 + mf * 16 + (lane & 15);
    #pragma unroll
    for (int p = 0; p < 2; p++)
        rB[p] = wn * 32 + p * 16 + (lane & 7) + ((lane >> 4) << 3);
    const int gA_hi = lane >> 4;          // A k-group select (0/1)
    const int gB_hi = (lane >> 3) & 1;    // B k-group select (0/1)

    load_tile(0);
    if (nt > 1) load_tile(1);

    for (int it = 0; it < nt; ++it) {
        const int s = it % 3;
        if (it < nt - 1) { CP_WAIT(1); } else { CP_WAIT(0); }
        __syncthreads();
        if (it + 2 < nt) load_tile(it + 2);

        const uint32_t sa = smb + (uint32_t)s * 32768u;
        const uint32_t sb = sa + 16384u;

        #pragma unroll
        for (int ks = 0; ks < 4; ks++) {
            uint32_t a[4][4], b[4][2];
            #pragma unroll
            for (int mf = 0; mf < 4; mf++) {
                int g = (2 * ks + gA_hi) ^ (rA[mf] & 7);
                uint32_t addr = sa + (uint32_t)(rA[mf] * 32 + g * 4) * 4u;
                LDSM_X4(a[mf][0], a[mf][1], a[mf][2], a[mf][3], addr);
            }
            #pragma unroll
            for (int p = 0; p < 2; p++) {
                int g = (2 * ks + gB_hi) ^ (rB[p] & 7);
                uint32_t addr = sb + (uint32_t)(rB[p] * 32 + g * 4) * 4u;
                LDSM_X4(b[2*p][0], b[2*p][1], b[2*p+1][0], b[2*p+1][1], addr);
            }
            #pragma unroll
            for (int mf = 0; mf < 4; mf++)
                #pragma unroll
                for (int nf = 0; nf < 4; nf++)
                    mma_tf32(acc[mf][nf], a[mf], b[nf]);
        }
    }

    // ---- epilogue (register accumulators) ----
    #pragma unroll
    for (int mf = 0; mf < 4; mf++) {
        #pragma unroll
        for (int nf = 0; nf < 4; nf++) {
            int lrow = wm * 64 + mf * 16 + (lane >> 2);
            int lcol = wn * 32 + nf * 8 + 2 * (lane & 3);
            float sb0 = sbias[lcol], sb1 = sbias[lcol + 1];
            #pragma unroll
            for (int rr = 0; rr < 2; rr++) {
                int gi   = m0 + lrow + rr * 8;
                int gcol = n0 + lcol;
                float2 v = make_float2(acc[mf][nf][2*rr]   + sb0,
                                       acc[mf][nf][2*rr+1] + sb1);
                if (EPI == 1) {
                    int w = gcol >> 10, r = gcol & 1023;
                    int h = r >> 6, d0 = r & 63;
                    int b_ = gi >> 11, t = gi & 2047;
                    if (w == 0) {
                        if (t >= (TT - CUT))
                            *(float2*)(C + ((((size_t)b_ * HH + h) * CUT)
                                        + (t - (TT - CUT))) * HS + d0) = v;
                    } else if (w == 1) {
                        *(float2*)((float*)R1 + (((size_t)b_ * HH + h) * TT + t) * HS + d0) = v;
                    } else {
                        *(float2*)((float*)R2 + (((size_t)b_ * HH + h) * TT + t) * HS + d0) = v;
                    }
                } else if (EPI == 2) {
                    int xrow = (gi >> 10) * TT + (TT - CUT) + (gi & 1023);
                    float2 xv = *(const float2*)(R1 + (size_t)xrow * CC + gcol);
                    *(float2*)(C + (size_t)gi * N + gcol) =
                        make_float2(v.x + xv.x, v.y + xv.y);
                } else if (EPI == 3) {
                    *(float2*)(C + (size_t)gi * N + gcol) =
                        make_float2(rtf32(gelu_exact(v.x)), rtf32(gelu_exact(v.y)));
                } else {   // EPI == 4
                    float2 rv = *(const float2*)(R1 + (size_t)gi * N + gcol);
                    *(float2*)(C + (size_t)gi * N + gcol) =
                        make_float2(v.x + rv.x, v.y + rv.y);
                }
            }
        }
    }
}

// ---------------------------------------------------------------------------
// Flash attention (FFMA; outputs tf32-rounded for the proj GEMM)
// ---------------------------------------------------------------------------
__global__ void __launch_bounds__(256, 2)
attn_kernel(const float* __restrict__ Qg, const float* __restrict__ Kg,
            const float* __restrict__ Vg, float* __restrict__ O)
{
    extern __shared__ float smf[];
    float* Qt   = smf;
    float* KtPs = smf + 64*64;
    float* Vs   = KtPs + 64*68;

    const int qt  = blockIdx.x;
    const int bh  = blockIdx.y;
    const int tid = threadIdx.x;
    const int tx  = tid & 15;
    const int ty  = tid >> 4;

    const size_t kvbase = (size_t)bh * TT * HS;
    const size_t qbase  = (size_t)bh * CUT * HS + (size_t)qt * 64 * HS;

    #pragma unroll
    for (int p = 0; p < 4; p++) {
        int lin4 = p * 256 + tid;
        int r = lin4 >> 4;
        int d = (lin4 & 15) * 4;
        float4 q4 = *(const float4*)(Qg + qbase + (size_t)r * HS + d);
        Qt[(d+0)*64 + r] = q4.x; Qt[(d+1)*64 + r] = q4.y;
        Qt[(d+2)*64 + r] = q4.z; Qt[(d+3)*64 + r] = q4.w;
    }

    float m[4], l[4], o[4][4];
    #pragma unroll
    for (int i = 0; i < 4; i++) {
        m[i] = -1e30f; l[i] = 0.f;
        #pragma unroll
        for (int j = 0; j < 4; j++) o[i][j] = 0.f;
    }

    const int ktmax = (TT - CUT) / 64 + qt;

    for (int kt = 0; kt <= ktmax; kt++) {
        __syncthreads();
        #pragma unroll
        for (int p = 0; p < 4; p++) {
            int lin4 = p * 256 + tid;
            int r = lin4 >> 4;
            int d = (lin4 & 15) * 4;
            const size_t gaddr = kvbase + (size_t)(kt*64 + r) * HS + d;
            float4 k4 = *(const float4*)(Kg + gaddr);
            KtPs[(d+0)*68 + r] = k4.x; KtPs[(d+1)*68 + r] = k4.y;
            KtPs[(d+2)*68 + r] = k4.z; KtPs[(d+3)*68 + r] = k4.w;
            float4 v4 = *(const float4*)(Vg + gaddr);
            *(float4*)&Vs[r*64 + d] = v4;
        }
        __syncthreads();

        float s[4][4];
        #pragma unroll
        for (int i = 0; i < 4; i++)
            #pragma unroll
            for (int j = 0; j < 4; j++) s[i][j] = 0.f;

        #pragma unroll 8
        for (int d = 0; d < 64; d++) {
            float4 qv = *(const float4*)&Qt[d*64 + ty*4];
            float4 kv = *(const float4*)&KtPs[d*68 + tx*4];
            float qa[4] = {qv.x, qv.y, qv.z, qv.w};
            float ka[4] = {kv.x, kv.y, kv.z, kv.w};
            #pragma unroll
            for (int i = 0; i < 4; i++)
                #pragma unroll
                for (int j = 0; j < 4; j++)
                    s[i][j] += qa[i] * ka[j];
        }
        #pragma unroll
        for (int i = 0; i < 4; i++)
            #pragma unroll
            for (int j = 0; j < 4; j++) s[i][j] *= SCALE;

        if (kt == ktmax) {
            #pragma unroll
            for (int i = 0; i < 4; i++)
                #pragma unroll
                for (int j = 0; j < 4; j++)
                    if (tx*4 + j > ty*4 + i) s[i][j] = -1e30f;
        }

        float mt[4];
        #pragma unroll
        for (int i = 0; i < 4; i++) {
            mt[i] = fmaxf(fmaxf(s[i][0], s[i][1]), fmaxf(s[i][2], s[i][3]));
            #pragma unroll
            for (int off = 8; off > 0; off >>= 1)
                mt[i] = fmaxf(mt[i], __shfl_xor_sync(0xffffffffu, mt[i], off, 16));
        }

        float ls[4];
        #pragma unroll
        for (int i = 0; i < 4; i++) {
            float mnew = fmaxf(m[i], mt[i]);
            float sc = __expf(m[i] - mnew);
            m[i] = mnew;
            float a = 0.f;
            #pragma unroll
            for (int j = 0; j < 4; j++) {
                s[i][j] = __expf(s[i][j] - mnew);
                a += s[i][j];
            }
            ls[i] = a;
            l[i] = l[i] * sc;
            #pragma unroll
            for (int j = 0; j < 4; j++) o[i][j] *= sc;
        }
        #pragma unroll
        for (int i = 0; i < 4; i++) {
            #pragma unroll
            for (int off = 8; off > 0; off >>= 1)
                ls[i] += __shfl_xor_sync(0xffffffffu, ls[i], off, 16);
            l[i] += ls[i];
        }

        __syncthreads();
        #pragma unroll
        for (int i = 0; i < 4; i++) {
            float4 pv = make_float4(s[i][0], s[i][1], s[i][2], s[i][3]);
            *(float4*)&KtPs[(ty*4 + i)*68 + tx*4] = pv;
        }
        __syncthreads();

        #pragma unroll 8
        for (int j = 0; j < 64; j++) {
            float4 vv = *(const float4*)&Vs[j*64 + tx*4];
            float va[4] = {vv.x, vv.y, vv.z, vv.w};
            float pr[4];
            #pragma unroll
            for (int i = 0; i < 4; i++) pr[i] = KtPs[(ty*4 + i)*68 + j];
            #pragma unroll
            for (int i = 0; i < 4; i++)
                #pragma unroll
                for (int jj = 0; jj < 4; jj++)
                    o[i][jj] += pr[i] * va[jj];
        }
    }

    const int b_ = bh >> 4, h_ = bh & 15;
    #pragma unroll
    for (int i = 0; i < 4; i++) {
        int srow = qt * 64 + ty * 4 + i;
        float inv = 1.0f / l[i];
        float4 ov = make_float4(rtf32(o[i][0]*inv), rtf32(o[i][1]*inv),
                                rtf32(o[i][2]*inv), rtf32(o[i][3]*inv));
        size_t addr = ((size_t)b_ * CUT + srow) * CC + h_ * HS + tx * 4;
        *(float4*)(O + addr) = ov;
    }
}

// ---------------------------------------------------------------------------
// Launch
// ---------------------------------------------------------------------------
extern "C" void kernel_launch(void* const* d_in, const int* in_sizes, int n_in,
                              void* d_out, int out_size)
{
    const float* x      = (const float*)d_in[0];
    const float* ln1_w  = (const float*)d_in[1];
    const float* ln1_b  = (const float*)d_in[2];
    const float* Wq     = (const float*)d_in[3];
    const float* bq     = (const float*)d_in[4];
    const float* Wk     = (const float*)d_in[5];
    const float* bk     = (const float*)d_in[6];
    const float* Wv     = (const float*)d_in[7];
    const float* bv     = (const float*)d_in[8];
    const float* proj_w = (const float*)d_in[9];
    const float* proj_b = (const float*)d_in[10];
    const float* ln2_w  = (const float*)d_in[11];
    const float* ln2_b  = (const float*)d_in[12];
    const float* lin1_w = (const float*)d_in[13];
    const float* lin1_b = (const float*)d_in[14];
    const float* lin2_w = (const float*)d_in[15];
    const float* lin2_b = (const float*)d_in[16];
    float* out = (float*)d_out;

    float *p_h, *p_K, *p_V, *p_Q, *p_o, *p_res, *p_h2, *p_a1;
    float *p_Wqkv, *p_Wp, *p_W1, *p_W2, *p_bqkv;
    cudaGetSymbolAddress((void**)&p_h,    g_h);
    cudaGetSymbolAddress((void**)&p_K,    g_K);
    cudaGetSymbolAddress((void**)&p_V,    g_V);
    cudaGetSymbolAddress((void**)&p_Q,    g_Q);
    cudaGetSymbolAddress((void**)&p_o,    g_o);
    cudaGetSymbolAddress((void**)&p_res,  g_res);
    cudaGetSymbolAddress((void**)&p_h2,   g_h2);
    cudaGetSymbolAddress((void**)&p_a1,   g_a1);
    cudaGetSymbolAddress((void**)&p_Wqkv, g_Wqkv);
    cudaGetSymbolAddress((void**)&p_Wp,   g_Wp);
    cudaGetSymbolAddress((void**)&p_W1,   g_W1);
    cudaGetSymbolAddress((void**)&p_W2,   g_W2);
    cudaGetSymbolAddress((void**)&p_bqkv, g_bqkv);

    static bool once = false;
    if (!once) {
        cudaFuncSetAttribute(attn_kernel,
                             cudaFuncAttributeMaxDynamicSharedMemorySize, 50176);
        cudaFuncSetAttribute(tc_gemm<1>,
                             cudaFuncAttributeMaxDynamicSharedMemorySize, GEMM_SMEM);
        cudaFuncSetAttribute(tc_gemm<2>,
                             cudaFuncAttributeMaxDynamicSharedMemorySize, GEMM_SMEM);
        cudaFuncSetAttribute(tc_gemm<3>,
                             cudaFuncAttributeMaxDynamicSharedMemorySize, GEMM_SMEM);
        cudaFuncSetAttribute(tc_gemm<4>,
                             cudaFuncAttributeMaxDynamicSharedMemorySize, GEMM_SMEM);
        once = true;
    }

    // weight repack (transpose + tf32 round) + bias pack + LN1
    qkv_tr_kernel<<<dim3(2, 32, 48), dim3(32, 8)>>>(Wq, Wk, Wv, p_Wqkv);
    tr_kernel<<<dim3(32, 32),  dim3(32, 8)>>>(proj_w, p_Wp, CC, CC);
    tr_kernel<<<dim3(128, 32), dim3(32, 8)>>>(lin1_w, p_W1, CC, 4*CC);
    tr_kernel<<<dim3(32, 128), dim3(32, 8)>>>(lin2_w, p_W2, 4*CC, CC);
    bias_pack_kernel<<<3, CC>>>(bq, bk, bv, p_bqkv);
    ln_kernel<<<ROWS_FULL, 256>>>(x, p_h, ln1_w, ln1_b);

    // fused QKV: [8192, 3072] = h @ Wqkv^T, scatter epilogue
    tc_gemm<1><<<dim3(3072/128, ROWS_FULL/128), 256, GEMM_SMEM>>>(
        p_h, p_Wqkv, p_Q, p_bqkv, p_K, p_V, ROWS_FULL, 3*CC, CC);

    // attention
    attn_kernel<<<dim3(CUT/64, BB*HH), 256, 50176>>>(p_Q, p_K, p_V, p_o);

    // proj + residual(x, last-cut rows) -> g_res
    tc_gemm<2><<<dim3(CC/128, ROWS_CUT/128), 256, GEMM_SMEM>>>(
        p_o, p_Wp, p_res, proj_b, x, nullptr, ROWS_CUT, CC, CC);

    // LN2
    ln_kernel<<<ROWS_CUT, 256>>>(p_res, p_h2, ln2_w, ln2_b);

    // MLP
    tc_gemm<3><<<dim3(4*CC/128, ROWS_CUT/128), 256, GEMM_SMEM>>>(
        p_h2, p_W1, p_a1, lin1_b, nullptr, nullptr, ROWS_CUT, 4*CC, CC);
    tc_gemm<4><<<dim3(CC/128, ROWS_CUT/128), 256, GEMM_SMEM>>>(
        p_a1, p_W2, out, lin2_b, p_res, nullptr, ROWS_CUT, CC, 4*CC);
}

// round 9
// speedup vs baseline: 4.0490x; 1.6818x over previous
#include <cuda_runtime.h>
#include <cuda_bf16.h>
#include <cstdint>
#include <math.h>

// ---------------------------------------------------------------------------
// Problem constants
// ---------------------------------------------------------------------------
#define BB   4
#define TT   2048
#define CC   1024
#define HH   16
#define HS   64
#define CUT  1024
#define ROWS_FULL (BB*TT)   // 8192
#define ROWS_CUT  (BB*CUT)  // 4096
#define SCALE 0.03125f      // C^-0.5

// ---------------------------------------------------------------------------
// Scratch (device globals; no allocations allowed)
// ---------------------------------------------------------------------------
__device__ float g_h   [ROWS_FULL * CC];
__device__ float g_K   [BB*HH*TT*HS];
__device__ float g_V   [BB*HH*TT*HS];
__device__ float g_Vt  [BB*HH*HS*TT];     // V transposed [bh][d][t]
__device__ float g_Q   [BB*HH*CUT*HS];
__device__ float g_o   [ROWS_CUT * CC];
__device__ float g_res [ROWS_CUT * CC];
__device__ float g_h2  [ROWS_CUT * CC];
__device__ float g_a1  [ROWS_CUT * 4*CC];
__device__ float g_Wqkv[3 * CC * CC];     // [3072, 1024] K-major
__device__ float g_Wp  [CC * CC];
__device__ float g_W1  [4*CC * CC];
__device__ float g_W2  [CC * 4*CC];
__device__ float g_bqkv[3 * CC];

// ---------------------------------------------------------------------------
// Helpers
// ---------------------------------------------------------------------------
__device__ __forceinline__ uint32_t smem_u32(const void* p) {
    uint32_t a;
    asm("{ .reg .u64 t; cvta.to.shared.u64 t, %1; cvt.u32.u64 %0, t; }"
        : "=r"(a) : "l"(p));
    return a;
}
// round fp32 -> tf32 (nearest) so HW tf32 truncation is a no-op
__device__ __forceinline__ float rtf32(float x) {
    uint32_t u = __float_as_uint(x);
    u = (u + 0x1000u) & 0xFFFFE000u;
    return __uint_as_float(u);
}
__device__ __forceinline__ float gelu_exact(float x) {
    return 0.5f * x * (1.0f + erff(x * 0.70710678118654752440f));
}

#define CP_ASYNC16(dst, src) \
    asm volatile("cp.async.cg.shared.global [%0], [%1], 16;" :: "r"(dst), "l"(src))
#define CP_COMMIT() asm volatile("cp.async.commit_group;")
#define CP_WAIT(n)  asm volatile("cp.async.wait_group %0;" :: "n"(n))

#define LDSM_X4(r0, r1, r2, r3, a) \
    asm volatile("ldmatrix.sync.aligned.m8n8.x4.shared.b16 {%0,%1,%2,%3}, [%4];" \
        : "=r"(r0), "=r"(r1), "=r"(r2), "=r"(r3) : "r"(a))

__device__ __forceinline__ void mma_tf32(float* c, const uint32_t* a, const uint32_t* b) {
    asm volatile(
        "mma.sync.aligned.m16n8k8.row.col.f32.tf32.tf32.f32 "
        "{%0,%1,%2,%3}, {%4,%5,%6,%7}, {%8,%9}, {%0,%1,%2,%3};"
        : "+f"(c[0]), "+f"(c[1]), "+f"(c[2]), "+f"(c[3])
        : "r"(a[0]), "r"(a[1]), "r"(a[2]), "r"(a[3]), "r"(b[0]), "r"(b[1]));
}

// ---------------------------------------------------------------------------
// Transpose + round: dst[n*K+k] = rtf32(src[k*N+n])
// ---------------------------------------------------------------------------
__global__ void tr_kernel(const float* __restrict__ src, float* __restrict__ dst,
                          int K, int N)
{
    __shared__ float t[32][33];
    int k0 = blockIdx.y * 32, n0 = blockIdx.x * 32;
    int tx = threadIdx.x, ty = threadIdx.y;      // 32 x 8
    #pragma unroll
    for (int i = 0; i < 32; i += 8)
        t[ty + i][tx] = src[(size_t)(k0 + ty + i) * N + n0 + tx];
    __syncthreads();
    #pragma unroll
    for (int i = 0; i < 32; i += 8)
        dst[(size_t)(n0 + ty + i) * K + k0 + tx] = rtf32(t[tx][ty + i]);
}

// QKV: [H,C,HS] x3 -> [3072, 1024] K-major; batch z: w=z/16, h=z%16
__global__ void qkv_tr_kernel(const float* __restrict__ Wq,
                              const float* __restrict__ Wk,
                              const float* __restrict__ Wv,
                              float* __restrict__ dst)
{
    __shared__ float t[32][33];
    int z = blockIdx.z, w = z >> 4, h = z & 15;
    const float* W = (w == 0) ? Wq : ((w == 1) ? Wk : Wv);
    const float* src = W + (size_t)h * CC * HS;
    float* d = dst + (size_t)w * CC * CC + (size_t)(h * HS) * CC;
    int k0 = blockIdx.y * 32, n0 = blockIdx.x * 32;
    int tx = threadIdx.x, ty = threadIdx.y;
    #pragma unroll
    for (int i = 0; i < 32; i += 8)
        t[ty + i][tx] = src[(size_t)(k0 + ty + i) * HS + n0 + tx];
    __syncthreads();
    #pragma unroll
    for (int i = 0; i < 32; i += 8)
        d[(size_t)(n0 + ty + i) * CC + k0 + tx] = rtf32(t[tx][ty + i]);
}

__global__ void bias_pack_kernel(const float* __restrict__ bq,
                                 const float* __restrict__ bk,
                                 const float* __restrict__ bv,
                                 float* __restrict__ out)
{
    int w = blockIdx.x, i = threadIdx.x;
    const float* b = (w == 0) ? bq : ((w == 1) ? bk : bv);
    out[w * CC + i] = b[i];
}

// V [bh][t][d] -> Vt [bh][d][t]
__global__ void vtr_kernel(const float* __restrict__ V, float* __restrict__ Vt)
{
    __shared__ float t[32][33];
    int bh = blockIdx.z;
    int t0 = blockIdx.x * 32, d0 = blockIdx.y * 32;
    const float* src = V + (size_t)bh * TT * HS;
    float* dst = Vt + (size_t)bh * HS * TT;
    int tx = threadIdx.x, ty = threadIdx.y;
    #pragma unroll
    for (int i = 0; i < 32; i += 8)
        t[ty + i][tx] = src[(size_t)(t0 + ty + i) * HS + d0 + tx];
    __syncthreads();
    #pragma unroll
    for (int i = 0; i < 32; i += 8)
        dst[(size_t)(d0 + ty + i) * TT + t0 + tx] = t[tx][ty + i];
}

// ---------------------------------------------------------------------------
// LayerNorm (rounds output to tf32 — it only feeds GEMMs)
// ---------------------------------------------------------------------------
__global__ void ln_kernel(const float* __restrict__ in, float* __restrict__ out,
                          const float* __restrict__ w, const float* __restrict__ b)
{
    int row = blockIdx.x;
    int tid = threadIdx.x;
    const float4 x4 = ((const float4*)(in + (size_t)row * CC))[tid];
    float s  = x4.x + x4.y + x4.z + x4.w;
    float s2 = x4.x*x4.x + x4.y*x4.y + x4.z*x4.z + x4.w*x4.w;
    #pragma unroll
    for (int off = 16; off > 0; off >>= 1) {
        s  += __shfl_xor_sync(0xffffffffu, s,  off);
        s2 += __shfl_xor_sync(0xffffffffu, s2, off);
    }
    __shared__ float red[2][8];
    int wid = tid >> 5, lane = tid & 31;
    if (lane == 0) { red[0][wid] = s; red[1][wid] = s2; }
    __syncthreads();
    float ts = 0.f, ts2 = 0.f;
    #pragma unroll
    for (int i = 0; i < 8; i++) { ts += red[0][i]; ts2 += red[1][i]; }
    float mean = ts * (1.0f / CC);
    float var  = ts2 * (1.0f / CC) - mean * mean;
    float rstd = rsqrtf(var + 1e-5f);
    const float4 w4 = ((const float4*)w)[tid];
    const float4 b4 = ((const float4*)b)[tid];
    float4 o4;
    o4.x = rtf32((x4.x - mean) * rstd * w4.x + b4.x);
    o4.y = rtf32((x4.y - mean) * rstd * w4.y + b4.y);
    o4.z = rtf32((x4.z - mean) * rstd * w4.z + b4.z);
    o4.w = rtf32((x4.w - mean) * rstd * w4.w + b4.w);
    ((float4*)(out + (size_t)row * CC))[tid] = o4;
}

// ---------------------------------------------------------------------------
// Tensor-core tf32 GEMM via mma.sync (m16n8k8).
// CTA 128x128, BK=32, 256 threads: 8 warps 2(M)x4(N), warp tile 64x32.
// EPI: 1 = QKV scatter (+tf32 round), 2 = +x residual (row remap),
//      3 = gelu+round, 4 = +R1 residual
// ---------------------------------------------------------------------------
#define GEMM_SMEM (3 * 8192 * 4)   // 96 KB

template<int EPI>
__global__ void __launch_bounds__(256)
tc_gemm(const float* __restrict__ A, const float* __restrict__ Bt,
        float* __restrict__ C, const float* __restrict__ bias,
        const float* __restrict__ R1, const float* __restrict__ R2,
        int M, int N, int K)
{
    extern __shared__ float sm[];
    __shared__ float sbias[128];

    const int tid  = threadIdx.x;
    const int lane = tid & 31;
    const int warp = tid >> 5;
    const int wm   = warp & 1;
    const int wn   = warp >> 1;
    const int m0   = blockIdx.y * 128;
    const int n0   = blockIdx.x * 128;

    if (tid < 128) sbias[tid] = bias[n0 + tid];

    const uint32_t smb = smem_u32(sm);
    const int nt = K >> 5;

    auto load_tile = [&](int it) {
        const int s = it % 3;
        const uint32_t sa = smb + (uint32_t)s * 32768u;
        const uint32_t sb = sa + 16384u;
        const float* gA = A  + (size_t)it * 32;
        const float* gB = Bt + (size_t)it * 32;
        #pragma unroll
        for (int i = 0; i < 4; i++) {
            int lin = i * 256 + tid;
            int r = lin >> 3;
            int g = lin & 7;
            uint32_t off = (uint32_t)(r * 32 + ((g ^ (r & 7)) * 4)) * 4u;
            CP_ASYNC16(sa + off, gA + (size_t)(m0 + r) * K + g * 4);
            CP_ASYNC16(sb + off, gB + (size_t)(n0 + r) * K + g * 4);
        }
        CP_COMMIT();
    };

    float acc[4][4][4];
    #pragma unroll
    for (int i = 0; i < 4; i++)
        #pragma unroll
        for (int j = 0; j < 4; j++)
            #pragma unroll
            for (int k = 0; k < 4; k++) acc[i][j][k] = 0.f;

    int rA[4], rB[2];
    #pragma unroll
    for (int mf = 0; mf < 4; mf++) rA[mf] = wm * 64 + mf * 16 + (lane & 15);
    #pragma unroll
    for (int p = 0; p < 2; p++)
        rB[p] = wn * 32 + p * 16 + (lane & 7) + ((lane >> 4) << 3);
    const int gA_hi = lane >> 4;
    const int gB_hi = (lane >> 3) & 1;

    load_tile(0);
    if (nt > 1) load_tile(1);

    for (int it = 0; it < nt; ++it) {
        const int s = it % 3;
        if (it < nt - 1) { CP_WAIT(1); } else { CP_WAIT(0); }
        __syncthreads();
        if (it + 2 < nt) load_tile(it + 2);

        const uint32_t sa = smb + (uint32_t)s * 32768u;
        const uint32_t sb = sa + 16384u;

        #pragma unroll
        for (int ks = 0; ks < 4; ks++) {
            uint32_t a[4][4], b[4][2];
            #pragma unroll
            for (int mf = 0; mf < 4; mf++) {
                int g = (2 * ks + gA_hi) ^ (rA[mf] & 7);
                uint32_t addr = sa + (uint32_t)(rA[mf] * 32 + g * 4) * 4u;
                LDSM_X4(a[mf][0], a[mf][1], a[mf][2], a[mf][3], addr);
            }
            #pragma unroll
            for (int p = 0; p < 2; p++) {
                int g = (2 * ks + gB_hi) ^ (rB[p] & 7);
                uint32_t addr = sb + (uint32_t)(rB[p] * 32 + g * 4) * 4u;
                LDSM_X4(b[2*p][0], b[2*p][1], b[2*p+1][0], b[2*p+1][1], addr);
            }
            #pragma unroll
            for (int mf = 0; mf < 4; mf++)
                #pragma unroll
                for (int nf = 0; nf < 4; nf++)
                    mma_tf32(acc[mf][nf], a[mf], b[nf]);
        }
    }

    #pragma unroll
    for (int mf = 0; mf < 4; mf++) {
        #pragma unroll
        for (int nf = 0; nf < 4; nf++) {
            int lrow = wm * 64 + mf * 16 + (lane >> 2);
            int lcol = wn * 32 + nf * 8 + 2 * (lane & 3);
            float sb0 = sbias[lcol], sb1 = sbias[lcol + 1];
            #pragma unroll
            for (int rr = 0; rr < 2; rr++) {
                int gi   = m0 + lrow + rr * 8;
                int gcol = n0 + lcol;
                float2 v = make_float2(acc[mf][nf][2*rr]   + sb0,
                                       acc[mf][nf][2*rr+1] + sb1);
                if (EPI == 1) {
                    v.x = rtf32(v.x); v.y = rtf32(v.y);
                    int w = gcol >> 10, r = gcol & 1023;
                    int h = r >> 6, d0 = r & 63;
                    int b_ = gi >> 11, t = gi & 2047;
                    if (w == 0) {
                        if (t >= (TT - CUT))
                            *(float2*)(C + ((((size_t)b_ * HH + h) * CUT)
                                        + (t - (TT - CUT))) * HS + d0) = v;
                    } else if (w == 1) {
                        *(float2*)((float*)R1 + (((size_t)b_ * HH + h) * TT + t) * HS + d0) = v;
                    } else {
                        *(float2*)((float*)R2 + (((size_t)b_ * HH + h) * TT + t) * HS + d0) = v;
                    }
                } else if (EPI == 2) {
                    int xrow = (gi >> 10) * TT + (TT - CUT) + (gi & 1023);
                    float2 xv = *(const float2*)(R1 + (size_t)xrow * CC + gcol);
                    *(float2*)(C + (size_t)gi * N + gcol) =
                        make_float2(v.x + xv.x, v.y + xv.y);
                } else if (EPI == 3) {
                    *(float2*)(C + (size_t)gi * N + gcol) =
                        make_float2(rtf32(gelu_exact(v.x)), rtf32(gelu_exact(v.y)));
                } else {
                    float2 rv = *(const float2*)(R1 + (size_t)gi * N + gcol);
                    *(float2*)(C + (size_t)gi * N + gcol) =
                        make_float2(v.x + rv.x, v.y + rv.y);
                }
            }
        }
    }
}

// ---------------------------------------------------------------------------
// Tensor-core flash attention (tf32 mma for QK^T and PV).
// Grid (qt=16, bh=64), 128 threads (4 warps x 16 query rows).
// SMEM floats: QsPs[4096] | Ks[2][4096] | Vs[2][4096]  = 80KB
// Q fragments register-resident; P via swizzled SMEM roundtrip (QsPs reuse).
// ---------------------------------------------------------------------------
#define ATT_SMEM (20480 * 4)

__global__ void __launch_bounds__(128)
attn_tc(const float* __restrict__ Qg, const float* __restrict__ Kg,
        const float* __restrict__ Vtg, float* __restrict__ O)
{
    extern __shared__ float smf[];
    const int qt   = blockIdx.x;
    const int bh   = blockIdx.y;
    const int tid  = threadIdx.x;
    const int lane = tid & 31;
    const int warp = tid >> 5;
    const uint32_t sb = smem_u32(smf);
    const uint32_t sQP = sb;                       // Q tile, later P tile

    const float* Qbase = Qg  + ((size_t)bh * CUT + (size_t)qt * 64) * HS;
    const float* Kbase = Kg  + (size_t)bh * TT * HS;
    const float* Vbase = Vtg + (size_t)bh * HS * TT;

    // swizzled byte offset within a 64-float-row tile
    auto swb = [](int r, int g) {
        return (uint32_t)(r * 64 + ((g ^ (r & 7)) * 4)) * 4u;
    };

    // load Q tile (group A)
    #pragma unroll
    for (int it = 0; it < 8; it++) {
        int lin = it * 128 + tid;
        int r = lin >> 4, g = lin & 15;
        CP_ASYNC16(sQP + swb(r, g), Qbase + r * 64 + g * 4);
    }
    CP_COMMIT();

    auto load_kv = [&](int kt, int buf) {
        uint32_t kdst = sb + (uint32_t)(4096 + buf * 4096) * 4u;
        uint32_t vdst = sb + (uint32_t)(12288 + buf * 4096) * 4u;
        const float* ks = Kbase + (size_t)kt * 64 * 64;
        const float* vs = Vbase + (size_t)kt * 64;
        #pragma unroll
        for (int it = 0; it < 8; it++) {
            int lin = it * 128 + tid;
            int r = lin >> 4, g = lin & 15;
            CP_ASYNC16(kdst + swb(r, g), ks + (size_t)r * 64 + g * 4);
            CP_ASYNC16(vdst + swb(r, g), vs + (size_t)r * TT + g * 4);
        }
        CP_COMMIT();
    };

    load_kv(0, 0);
    CP_WAIT(1);            // Q ready
    __syncthreads();

    // Q fragments (register resident for the whole kernel)
    uint32_t qf[8][4];
    {
        int rA = warp * 16 + (lane & 15);
        #pragma unroll
        for (int ks = 0; ks < 8; ks++) {
            int g = (2 * ks + (lane >> 4)) ^ (rA & 7);
            uint32_t addr = sQP + (uint32_t)(rA * 64 + g * 4) * 4u;
            LDSM_X4(qf[ks][0], qf[ks][1], qf[ks][2], qf[ks][3], addr);
        }
    }

    float m[2] = {-1e30f, -1e30f}, l[2] = {0.f, 0.f};
    float oacc[8][4];
    #pragma unroll
    for (int nf = 0; nf < 8; nf++)
        #pragma unroll
        for (int e = 0; e < 4; e++) oacc[nf][e] = 0.f;

    const int rA_ld  = warp * 16 + (lane & 15);
    const int gA_hi  = lane >> 4;
    const int gB_hi  = (lane >> 3) & 1;
    int rB[4];
    #pragma unroll
    for (int p = 0; p < 4; p++)
        rB[p] = p * 16 + (lane & 7) + ((lane >> 4) << 3);

    const int ktmax = (TT - CUT) / 64 + qt;    // 16 + qt

    for (int kt = 0; kt <= ktmax; kt++) {
        const int buf = kt & 1;
        __syncthreads();                        // prev PV done before overwrite
        if (kt < ktmax) load_kv(kt + 1, buf ^ 1);
        if (kt < ktmax) { CP_WAIT(1); } else { CP_WAIT(0); }
        __syncthreads();                        // current tile visible

        const uint32_t kB = sb + (uint32_t)(4096 + buf * 4096) * 4u;
        const uint32_t vB = sb + (uint32_t)(12288 + buf * 4096) * 4u;

        // ---- S = Q K^T ----
        float sfr[8][4];
        #pragma unroll
        for (int nf = 0; nf < 8; nf++)
            #pragma unroll
            for (int e = 0; e < 4; e++) sfr[nf][e] = 0.f;

        #pragma unroll
        for (int ks = 0; ks < 8; ks++) {
            uint32_t b[8][2];
            #pragma unroll
            for (int p = 0; p < 4; p++) {
                int g = (2 * ks + gB_hi) ^ (rB[p] & 7);
                uint32_t addr = kB + (uint32_t)(rB[p] * 64 + g * 4) * 4u;
                LDSM_X4(b[2*p][0], b[2*p][1], b[2*p+1][0], b[2*p+1][1], addr);
            }
            #pragma unroll
            for (int nf = 0; nf < 8; nf++)
                mma_tf32(sfr[nf], qf[ks], b[nf]);
        }

        #pragma unroll
        for (int nf = 0; nf < 8; nf++)
            #pragma unroll
            for (int e = 0; e < 4; e++) sfr[nf][e] *= SCALE;

        // ---- mask (diagonal tile): within-tile col > row -> -inf ----
        if (kt == ktmax) {
            int r0 = warp * 16 + (lane >> 2);
            #pragma unroll
            for (int nf = 0; nf < 8; nf++) {
                int c0 = nf * 8 + 2 * (lane & 3);
                if (c0     > r0)     sfr[nf][0] = -1e30f;
                if (c0 + 1 > r0)     sfr[nf][1] = -1e30f;
                if (c0     > r0 + 8) sfr[nf][2] = -1e30f;
                if (c0 + 1 > r0 + 8) sfr[nf][3] = -1e30f;
            }
        }

        // ---- online softmax ----
        float mt[2] = {-1e30f, -1e30f};
        #pragma unroll
        for (int nf = 0; nf < 8; nf++) {
            mt[0] = fmaxf(mt[0], fmaxf(sfr[nf][0], sfr[nf][1]));
            mt[1] = fmaxf(mt[1], fmaxf(sfr[nf][2], sfr[nf][3]));
        }
        #pragma unroll
        for (int i = 0; i < 2; i++) {
            mt[i] = fmaxf(mt[i], __shfl_xor_sync(0xffffffffu, mt[i], 1));
            mt[i] = fmaxf(mt[i], __shfl_xor_sync(0xffffffffu, mt[i], 2));
        }
        float sc[2], rs[2];
        #pragma unroll
        for (int i = 0; i < 2; i++) {
            float mnew = fmaxf(m[i], mt[i]);
            sc[i] = __expf(m[i] - mnew);
            m[i]  = mnew;
            rs[i] = 0.f;
        }
        #pragma unroll
        for (int nf = 0; nf < 8; nf++) {
            sfr[nf][0] = __expf(sfr[nf][0] - m[0]);
            sfr[nf][1] = __expf(sfr[nf][1] - m[0]);
            sfr[nf][2] = __expf(sfr[nf][2] - m[1]);
            sfr[nf][3] = __expf(sfr[nf][3] - m[1]);
            rs[0] += sfr[nf][0] + sfr[nf][1];
            rs[1] += sfr[nf][2] + sfr[nf][3];
        }
        #pragma unroll
        for (int i = 0; i < 2; i++) {
            rs[i] += __shfl_xor_sync(0xffffffffu, rs[i], 1);
            rs[i] += __shfl_xor_sync(0xffffffffu, rs[i], 2);
            l[i] = l[i] * sc[i] + rs[i];
        }
        #pragma unroll
        for (int nf = 0; nf < 8; nf++) {
            oacc[nf][0] *= sc[0]; oacc[nf][1] *= sc[0];
            oacc[nf][2] *= sc[1]; oacc[nf][3] *= sc[1];
        }

        // ---- store P (tf32-rounded) into QsPs, swizzled ----
        {
            int r0 = warp * 16 + (lane >> 2);
            #pragma unroll
            for (int nf = 0; nf < 8; nf++) {
                int j0 = nf * 8 + 2 * (lane & 3);
                int g = j0 >> 2, o4 = j0 & 3;
                int i1 = r0 * 64 + ((g ^ (r0 & 7)) * 4 + o4);
                int r2 = r0 + 8;
                int i2 = r2 * 64 + ((g ^ (r2 & 7)) * 4 + o4);
                *(float2*)(smf + i1) = make_float2(rtf32(sfr[nf][0]), rtf32(sfr[nf][1]));
                *(float2*)(smf + i2) = make_float2(rtf32(sfr[nf][2]), rtf32(sfr[nf][3]));
            }
        }
        __syncthreads();

        // ---- O += P V  (A = P from SMEM, B = Vt) ----
        #pragma unroll
        for (int ks = 0; ks < 8; ks++) {
            uint32_t a[4];
            {
                int g = (2 * ks + gA_hi) ^ (rA_ld & 7);
                uint32_t addr = sQP + (uint32_t)(rA_ld * 64 + g * 4) * 4u;
                LDSM_X4(a[0], a[1], a[2], a[3], addr);
            }
            uint32_t b[8][2];
            #pragma unroll
            for (int p = 0; p < 4; p++) {
                int g = (2 * ks + gB_hi) ^ (rB[p] & 7);
                uint32_t addr = vB + (uint32_t)(rB[p] * 64 + g * 4) * 4u;
                LDSM_X4(b[2*p][0], b[2*p][1], b[2*p+1][0], b[2*p+1][1], addr);
            }
            #pragma unroll
            for (int nf = 0; nf < 8; nf++)
                mma_tf32(oacc[nf], a, b[nf]);
        }
    }

    // ---- write O (head-concat layout), tf32-rounded for proj GEMM ----
    const int b_ = bh >> 4, h_ = bh & 15;
    const int r0 = warp * 16 + (lane >> 2);
    float inv0 = 1.0f / l[0], inv1 = 1.0f / l[1];
    #pragma unroll
    for (int nf = 0; nf < 8; nf++) {
        int j0 = nf * 8 + 2 * (lane & 3);
        size_t a1 = ((size_t)b_ * CUT + qt * 64 + r0) * CC + h_ * HS + j0;
        size_t a2 = ((size_t)b_ * CUT + qt * 64 + r0 + 8) * CC + h_ * HS + j0;
        *(float2*)(O + a1) = make_float2(rtf32(oacc[nf][0] * inv0),
                                         rtf32(oacc[nf][1] * inv0));
        *(float2*)(O + a2) = make_float2(rtf32(oacc[nf][2] * inv1),
                                         rtf32(oacc[nf][3] * inv1));
    }
}

// ---------------------------------------------------------------------------
// Launch
// ---------------------------------------------------------------------------
extern "C" void kernel_launch(void* const* d_in, const int* in_sizes, int n_in,
                              void* d_out, int out_size)
{
    const float* x      = (const float*)d_in[0];
    const float* ln1_w  = (const float*)d_in[1];
    const float* ln1_b  = (const float*)d_in[2];
    const float* Wq     = (const float*)d_in[3];
    const float* bq     = (const float*)d_in[4];
    const float* Wk     = (const float*)d_in[5];
    const float* bk     = (const float*)d_in[6];
    const float* Wv     = (const float*)d_in[7];
    const float* bv     = (const float*)d_in[8];
    const float* proj_w = (const float*)d_in[9];
    const float* proj_b = (const float*)d_in[10];
    const float* ln2_w  = (const float*)d_in[11];
    const float* ln2_b  = (const float*)d_in[12];
    const float* lin1_w = (const float*)d_in[13];
    const float* lin1_b = (const float*)d_in[14];
    const float* lin2_w = (const float*)d_in[15];
    const float* lin2_b = (const float*)d_in[16];
    float* out = (float*)d_out;

    float *p_h, *p_K, *p_V, *p_Vt, *p_Q, *p_o, *p_res, *p_h2, *p_a1;
    float *p_Wqkv, *p_Wp, *p_W1, *p_W2, *p_bqkv;
    cudaGetSymbolAddress((void**)&p_h,    g_h);
    cudaGetSymbolAddress((void**)&p_K,    g_K);
    cudaGetSymbolAddress((void**)&p_V,    g_V);
    cudaGetSymbolAddress((void**)&p_Vt,   g_Vt);
    cudaGetSymbolAddress((void**)&p_Q,    g_Q);
    cudaGetSymbolAddress((void**)&p_o,    g_o);
    cudaGetSymbolAddress((void**)&p_res,  g_res);
    cudaGetSymbolAddress((void**)&p_h2,   g_h2);
    cudaGetSymbolAddress((void**)&p_a1,   g_a1);
    cudaGetSymbolAddress((void**)&p_Wqkv, g_Wqkv);
    cudaGetSymbolAddress((void**)&p_Wp,   g_Wp);
    cudaGetSymbolAddress((void**)&p_W1,   g_W1);
    cudaGetSymbolAddress((void**)&p_W2,   g_W2);
    cudaGetSymbolAddress((void**)&p_bqkv, g_bqkv);

    static bool once = false;
    if (!once) {
        cudaFuncSetAttribute(attn_tc,
                             cudaFuncAttributeMaxDynamicSharedMemorySize, ATT_SMEM);
        cudaFuncSetAttribute(tc_gemm<1>,
                             cudaFuncAttributeMaxDynamicSharedMemorySize, GEMM_SMEM);
        cudaFuncSetAttribute(tc_gemm<2>,
                             cudaFuncAttributeMaxDynamicSharedMemorySize, GEMM_SMEM);
        cudaFuncSetAttribute(tc_gemm<3>,
                             cudaFuncAttributeMaxDynamicSharedMemorySize, GEMM_SMEM);
        cudaFuncSetAttribute(tc_gemm<4>,
                             cudaFuncAttributeMaxDynamicSharedMemorySize, GEMM_SMEM);
        once = true;
    }

    // weight repack (transpose + tf32 round) + bias pack + LN1
    qkv_tr_kernel<<<dim3(2, 32, 48), dim3(32, 8)>>>(Wq, Wk, Wv, p_Wqkv);
    tr_kernel<<<dim3(32, 32),  dim3(32, 8)>>>(proj_w, p_Wp, CC, CC);
    tr_kernel<<<dim3(128, 32), dim3(32, 8)>>>(lin1_w, p_W1, CC, 4*CC);
    tr_kernel<<<dim3(32, 128), dim3(32, 8)>>>(lin2_w, p_W2, 4*CC, CC);
    bias_pack_kernel<<<3, CC>>>(bq, bk, bv, p_bqkv);
    ln_kernel<<<ROWS_FULL, 256>>>(x, p_h, ln1_w, ln1_b);

    // fused QKV: [8192, 3072] = h @ Wqkv^T, scatter epilogue (tf32-rounded)
    tc_gemm<1><<<dim3(3072/128, ROWS_FULL/128), 256, GEMM_SMEM>>>(
        p_h, p_Wqkv, p_Q, p_bqkv, p_K, p_V, ROWS_FULL, 3*CC, CC);

    // V transpose for PV mma
    vtr_kernel<<<dim3(TT/32, HS/32, BB*HH), dim3(32, 8)>>>(p_V, p_Vt);

    // attention (tensor cores)
    attn_tc<<<dim3(CUT/64, BB*HH), 128, ATT_SMEM>>>(p_Q, p_K, p_Vt, p_o);

    // proj + residual(x, last-cut rows) -> g_res
    tc_gemm<2><<<dim3(CC/128, ROWS_CUT/128), 256, GEMM_SMEM>>>(
        p_o, p_Wp, p_res, proj_b, x, nullptr, ROWS_CUT, CC, CC);

    // LN2
    ln_kernel<<<ROWS_CUT, 256>>>(p_res, p_h2, ln2_w, ln2_b);

    // MLP
    tc_gemm<3><<<dim3(4*CC/128, ROWS_CUT/128), 256, GEMM_SMEM>>>(
        p_h2, p_W1, p_a1, lin1_b, nullptr, nullptr, ROWS_CUT, 4*CC, CC);
    tc_gemm<4><<<dim3(CC/128, ROWS_CUT/128), 256, GEMM_SMEM>>>(
        p_a1, p_W2, out, lin2_b, p_res, nullptr, ROWS_CUT, CC, 4*CC);
}